// round 2
// baseline (speedup 1.0000x reference)
#include <cuda_runtime.h>
#include <math.h>

// ---------------------------------------------------------------------------
// Complex 2-layer MAP graph convolution, fp32.
//   w = ws * exp(i * q * (ent + cc))           per edge
//   Z = A_complex @ X_complex                  (CSR gather SpMM, no atomics)
//   l1r = Zr @ W1^T            (biases cancel: rr-ii)
//   l1i = Zi @ W1^T + 2*b1     (biases double: ir+ri)
//   comrelu mask from real part
//   ... layer 2 ...
//   out = [l2r | l2i] @ W3^T + b3
// ---------------------------------------------------------------------------

namespace {
constexpr int NN = 50000;     // nodes
constexpr int NE = 1600000;   // edges
constexpr int KF = 256;       // FEAT == HID
constexpr int NO = 64;        // OUT
}

// scratch (device globals: allocation-free by rule)
__device__ int   g_deg[NN];
__device__ int   g_cursor[NN];
__device__ int   g_rowstart[NN + 1];
__device__ int   g_ccol[NE];
__device__ float g_cwr[NE];
__device__ float g_cwi[NE];
__device__ float g_Zr[(size_t)NN * KF];
__device__ float g_Zi[(size_t)NN * KF];
__device__ float g_Hr[(size_t)NN * KF];
__device__ float g_Hi[(size_t)NN * KF];

// ---------------------------------------------------------------------------
__global__ void k_zero_deg() {
    int i = blockIdx.x * blockDim.x + threadIdx.x;
    if (i < NN) g_deg[i] = 0;
}

__global__ void k_hist(const int* __restrict__ row, int E) {
    int i = blockIdx.x * blockDim.x + threadIdx.x;
    if (i < E) atomicAdd(&g_deg[row[i]], 1);
}

// single-block exclusive scan over 50000 degrees -> rowstart & cursor
__global__ void k_scan() {
    __shared__ int sh[1024];
    __shared__ int s_run;
    if (threadIdx.x == 0) s_run = 0;
    __syncthreads();
    for (int base = 0; base < NN; base += 1024) {
        int i = base + (int)threadIdx.x;
        int v = (i < NN) ? g_deg[i] : 0;
        sh[threadIdx.x] = v;
        __syncthreads();
        for (int ofs = 1; ofs < 1024; ofs <<= 1) {
            int t = (threadIdx.x >= (unsigned)ofs) ? sh[threadIdx.x - ofs] : 0;
            __syncthreads();
            sh[threadIdx.x] += t;
            __syncthreads();
        }
        int run = s_run;
        if (i < NN) {
            int excl = run + sh[threadIdx.x] - v;
            g_rowstart[i] = excl;
            g_cursor[i]   = excl;
        }
        __syncthreads();
        if (threadIdx.x == 0) s_run = run + sh[1023];
        __syncthreads();
    }
    if (threadIdx.x == 0) g_rowstart[NN] = s_run;
}

// per-edge trig weights + CSR scatter
__global__ void k_scatter(const int* __restrict__ row, const int* __restrict__ col,
                          const float* __restrict__ ws, const float* __restrict__ ent,
                          const float* __restrict__ cc, const float* __restrict__ q, int E) {
    int i = blockIdx.x * blockDim.x + threadIdx.x;
    if (i >= E) return;
    float ph = q[0] * (ent[i] + cc[i]);
    float s, c;
    sincosf(ph, &s, &c);
    float w = ws[i];
    int p = atomicAdd(&g_cursor[row[i]], 1);
    g_ccol[p] = col[i];
    g_cwr[p] = w * c;
    g_cwi[p] = w * s;
}

// ---------------------------------------------------------------------------
// CSR gather complex SpMM: warp handles (row, 128-feature chunk); lane owns
// 4 consecutive floats (float4). Register accumulation, no atomics.
// ---------------------------------------------------------------------------
__global__ void k_spmm(const float* __restrict__ Xr, const float* __restrict__ Xi,
                       float* __restrict__ Zr, float* __restrict__ Zi) {
    int gw   = (blockIdx.x * blockDim.x + threadIdx.x) >> 5;
    int lane = threadIdx.x & 31;
    int r = gw >> 1;
    if (r >= NN) return;
    int off = ((gw & 1) << 7) + (lane << 2);

    int s = g_rowstart[r], e = g_rowstart[r + 1];
    float4 ar = make_float4(0.f, 0.f, 0.f, 0.f);
    float4 ai = make_float4(0.f, 0.f, 0.f, 0.f);
    for (int j = s; j < e; j++) {
        int   c  = g_ccol[j];
        float wr = g_cwr[j];
        float wi = g_cwi[j];
        const float4 xr = *(const float4*)(Xr + (size_t)c * KF + off);
        const float4 xi = *(const float4*)(Xi + (size_t)c * KF + off);
        ar.x = fmaf(wr, xr.x, fmaf(-wi, xi.x, ar.x));
        ar.y = fmaf(wr, xr.y, fmaf(-wi, xi.y, ar.y));
        ar.z = fmaf(wr, xr.z, fmaf(-wi, xi.z, ar.z));
        ar.w = fmaf(wr, xr.w, fmaf(-wi, xi.w, ar.w));
        ai.x = fmaf(wi, xr.x, fmaf(wr, xi.x, ai.x));
        ai.y = fmaf(wi, xr.y, fmaf(wr, xi.y, ai.y));
        ai.z = fmaf(wi, xr.z, fmaf(wr, xi.z, ai.z));
        ai.w = fmaf(wi, xr.w, fmaf(wr, xi.w, ai.w));
    }
    *(float4*)(Zr + (size_t)r * KF + off) = ar;
    *(float4*)(Zi + (size_t)r * KF + off) = ai;
}

// ---------------------------------------------------------------------------
// Fused dual SGEMM: Or = mask*(Ar@W^T + bscr*b), Oi = mask*(Ai@W^T + bsci*b)
// mask = (real part >= 0). BM=128 BN=64 BK=16, 256 thr, thread tile 8x4 (x2).
// W row-major [H, K] (so out = A @ W^T reads both operands K-contiguous).
// ---------------------------------------------------------------------------
__global__ void k_gemm_dual(const float* __restrict__ Ar, const float* __restrict__ Ai,
                            const float* __restrict__ W,  const float* __restrict__ bias,
                            float* __restrict__ Or, float* __restrict__ Oi,
                            float bscr, float bsci) {
    constexpr int BM = 128, BN = 64, BK = 16;
    __shared__ float As_r[BK][BM + 4];
    __shared__ float As_i[BK][BM + 4];
    __shared__ float Bs[BK][BN + 4];
    int tid = threadIdx.x;
    int tx = tid & 15, ty = tid >> 4;
    int row0 = blockIdx.x * BM;
    int col0 = blockIdx.y * BN;
    float accr[8][4] = {}, acci[8][4] = {};

    for (int k0 = 0; k0 < KF; k0 += BK) {
#pragma unroll
        for (int l = 0; l < 2; l++) {
            int idx = tid + l * 256;
            int r = idx >> 2, kq = idx & 3;
            int gr = row0 + r; if (gr >= NN) gr = NN - 1;
            const float4 vr = *(const float4*)(Ar + (size_t)gr * KF + k0 + kq * 4);
            const float4 vi = *(const float4*)(Ai + (size_t)gr * KF + k0 + kq * 4);
            As_r[kq*4+0][r] = vr.x; As_r[kq*4+1][r] = vr.y;
            As_r[kq*4+2][r] = vr.z; As_r[kq*4+3][r] = vr.w;
            As_i[kq*4+0][r] = vi.x; As_i[kq*4+1][r] = vi.y;
            As_i[kq*4+2][r] = vi.z; As_i[kq*4+3][r] = vi.w;
        }
        {
            int r = tid >> 2, kq = tid & 3;
            const float4 v = *(const float4*)(W + (size_t)(col0 + r) * KF + k0 + kq * 4);
            Bs[kq*4+0][r] = v.x; Bs[kq*4+1][r] = v.y;
            Bs[kq*4+2][r] = v.z; Bs[kq*4+3][r] = v.w;
        }
        __syncthreads();
#pragma unroll
        for (int k = 0; k < BK; k++) {
            float4 b0 = *(const float4*)&Bs[k][tx * 4];
            float4 a0 = *(const float4*)&As_r[k][ty * 8];
            float4 a1 = *(const float4*)&As_r[k][ty * 8 + 4];
            float4 c0 = *(const float4*)&As_i[k][ty * 8];
            float4 c1 = *(const float4*)&As_i[k][ty * 8 + 4];
            float ar[8] = {a0.x, a0.y, a0.z, a0.w, a1.x, a1.y, a1.z, a1.w};
            float ai[8] = {c0.x, c0.y, c0.z, c0.w, c1.x, c1.y, c1.z, c1.w};
            float bb[4] = {b0.x, b0.y, b0.z, b0.w};
#pragma unroll
            for (int i = 0; i < 8; i++)
#pragma unroll
                for (int j = 0; j < 4; j++) {
                    accr[i][j] = fmaf(ar[i], bb[j], accr[i][j]);
                    acci[i][j] = fmaf(ai[i], bb[j], acci[i][j]);
                }
        }
        __syncthreads();
    }

    const float4 bv = *(const float4*)(bias + col0 + tx * 4);
    float bvals[4] = {bv.x, bv.y, bv.z, bv.w};
#pragma unroll
    for (int i = 0; i < 8; i++) {
        int gr = row0 + ty * 8 + i;
        if (gr < NN) {
            float rr[4], ii[4];
#pragma unroll
            for (int j = 0; j < 4; j++) {
                float rv = accr[i][j] + bscr * bvals[j];
                float iv = acci[i][j] + bsci * bvals[j];
                float m = (rv >= 0.f) ? 1.f : 0.f;
                rr[j] = rv * m;
                ii[j] = iv * m;
            }
            *(float4*)(Or + (size_t)gr * KF + col0 + tx * 4) = make_float4(rr[0], rr[1], rr[2], rr[3]);
            *(float4*)(Oi + (size_t)gr * KF + col0 + tx * 4) = make_float4(ii[0], ii[1], ii[2], ii[3]);
        }
    }
}

// ---------------------------------------------------------------------------
// Head: out[n, o] = sum_k Hr[n,k]*W3[o,k] + Hi[n,k]*W3[o,256+k] + b3[o]
// K = 512 loop switching A source at k=256. BM=128 BN=64 BK=16.
// ---------------------------------------------------------------------------
__global__ void k_gemm_head(const float* __restrict__ Hr, const float* __restrict__ Hi,
                            const float* __restrict__ W3, const float* __restrict__ b3,
                            float* __restrict__ out) {
    constexpr int BM = 128, BN = 64, BK = 16, K2 = 512;
    __shared__ float As[BK][BM + 4];
    __shared__ float Bs[BK][BN + 4];
    int tid = threadIdx.x;
    int tx = tid & 15, ty = tid >> 4;
    int row0 = blockIdx.x * BM;
    float acc[8][4] = {};

    for (int k0 = 0; k0 < K2; k0 += BK) {
        const float* A = (k0 < 256) ? Hr : Hi;
        int ko = (k0 < 256) ? k0 : (k0 - 256);
#pragma unroll
        for (int l = 0; l < 2; l++) {
            int idx = tid + l * 256;
            int r = idx >> 2, kq = idx & 3;
            int gr = row0 + r; if (gr >= NN) gr = NN - 1;
            const float4 v = *(const float4*)(A + (size_t)gr * KF + ko + kq * 4);
            As[kq*4+0][r] = v.x; As[kq*4+1][r] = v.y;
            As[kq*4+2][r] = v.z; As[kq*4+3][r] = v.w;
        }
        {
            int r = tid >> 2, kq = tid & 3;
            const float4 v = *(const float4*)(W3 + (size_t)r * K2 + k0 + kq * 4);
            Bs[kq*4+0][r] = v.x; Bs[kq*4+1][r] = v.y;
            Bs[kq*4+2][r] = v.z; Bs[kq*4+3][r] = v.w;
        }
        __syncthreads();
#pragma unroll
        for (int k = 0; k < BK; k++) {
            float4 b0 = *(const float4*)&Bs[k][tx * 4];
            float4 a0 = *(const float4*)&As[k][ty * 8];
            float4 a1 = *(const float4*)&As[k][ty * 8 + 4];
            float a[8] = {a0.x, a0.y, a0.z, a0.w, a1.x, a1.y, a1.z, a1.w};
            float bb[4] = {b0.x, b0.y, b0.z, b0.w};
#pragma unroll
            for (int i = 0; i < 8; i++)
#pragma unroll
                for (int j = 0; j < 4; j++)
                    acc[i][j] = fmaf(a[i], bb[j], acc[i][j]);
        }
        __syncthreads();
    }

    const float4 bv = *(const float4*)(b3 + tx * 4);
#pragma unroll
    for (int i = 0; i < 8; i++) {
        int gr = row0 + ty * 8 + i;
        if (gr < NN) {
            float4 o = make_float4(acc[i][0] + bv.x, acc[i][1] + bv.y,
                                   acc[i][2] + bv.z, acc[i][3] + bv.w);
            *(float4*)(out + (size_t)gr * NO + tx * 4) = o;
        }
    }
}

// ---------------------------------------------------------------------------
extern "C" void kernel_launch(void* const* d_in, const int* in_sizes, int n_in,
                              void* d_out, int out_size) {
    const float* real = (const float*)d_in[0];
    const float* imag = (const float*)d_in[1];
    const int*   row  = (const int*)d_in[2];
    const int*   col  = (const int*)d_in[3];
    const float* ws   = (const float*)d_in[4];
    const float* ent  = (const float*)d_in[5];
    const float* cc   = (const float*)d_in[6];
    const float* q    = (const float*)d_in[7];
    const float* W1   = (const float*)d_in[8];
    const float* b1   = (const float*)d_in[9];
    const float* W2   = (const float*)d_in[10];
    const float* b2   = (const float*)d_in[11];
    const float* W3   = (const float*)d_in[12];
    const float* b3   = (const float*)d_in[13];
    float* out = (float*)d_out;
    const int E = in_sizes[2];

    void *pZr, *pZi, *pHr, *pHi;
    cudaGetSymbolAddress(&pZr, g_Zr);
    cudaGetSymbolAddress(&pZi, g_Zi);
    cudaGetSymbolAddress(&pHr, g_Hr);
    cudaGetSymbolAddress(&pHi, g_Hi);
    float* Zr = (float*)pZr; float* Zi = (float*)pZi;
    float* Hr = (float*)pHr; float* Hi = (float*)pHi;

    // CSR build
    k_zero_deg<<<(NN + 255) / 256, 256>>>();
    k_hist<<<(E + 255) / 256, 256>>>(row, E);
    k_scan<<<1, 1024>>>();
    k_scatter<<<(E + 255) / 256, 256>>>(row, col, ws, ent, cc, q, E);

    const int spmm_blocks = (NN * 2 + 7) / 8;   // 8 warps/block, 2 chunks/row
    dim3 gemm_grid((NN + 127) / 128, KF / 64);

    // layer 1
    k_spmm<<<spmm_blocks, 256>>>(real, imag, Zr, Zi);
    k_gemm_dual<<<gemm_grid, 256>>>(Zr, Zi, W1, b1, Hr, Hi, 0.f, 2.f);
    // layer 2
    k_spmm<<<spmm_blocks, 256>>>(Hr, Hi, Zr, Zi);
    k_gemm_dual<<<gemm_grid, 256>>>(Zr, Zi, W2, b2, Hr, Hi, 0.f, 2.f);
    // head
    k_gemm_head<<<(NN + 127) / 128, 256>>>(Hr, Hi, W3, b3, out);
}

// round 9
// speedup vs baseline: 1.5042x; 1.5042x over previous
#include <cuda_runtime.h>
#include <math.h>
#include <stdint.h>

// ---------------------------------------------------------------------------
// Complex 2-layer MAP graph convolution, fp32 (R2-exact numerics).
//   CSR build -> complex SpMM (fp32, register acc, MLP-8 unrolled gathers)
//   -> fp32 GEMM via packed fma.rn.f32x2 (FFMA2, 2x fma-pipe throughput),
//      register-staged prefetch pipeline -> head GEMM.
// R8: all mma.sync variants fail (tensor-core accumulation noise ~1e-6 is
//     amplified by comrelu mask flips past 1e-3). FFMA serial-k accumulation
//     (bit-identical to the R2 pass) is required; FFMA2 doubles its rate.
// ---------------------------------------------------------------------------

namespace {
constexpr int NN = 50000;     // nodes
constexpr int NE = 1600000;   // edges
constexpr int KF = 256;       // FEAT == HID
constexpr int NO = 64;        // OUT
}

// scratch (device globals: allocation-free by rule)
__device__ int   g_deg[NN];
__device__ int   g_cursor[NN];
__device__ int   g_rowstart[NN + 1];
__device__ int   g_ccol[NE];
__device__ float g_cwr[NE];
__device__ float g_cwi[NE];
__device__ float g_Zr[(size_t)NN * KF];
__device__ float g_Zi[(size_t)NN * KF];
__device__ float g_Hr[(size_t)NN * KF];
__device__ float g_Hi[(size_t)NN * KF];

// ---------------------------------------------------------------------------
// f32x2 packed helpers (Blackwell base ISA; RN per element == scalar fmaf)
// ---------------------------------------------------------------------------
__device__ __forceinline__ uint64_t pk2(float lo, float hi) {
    uint64_t r; asm("mov.b64 %0, {%1, %2};" : "=l"(r) : "f"(lo), "f"(hi)); return r;
}
__device__ __forceinline__ void upk2(uint64_t v, float& lo, float& hi) {
    asm("mov.b64 {%0, %1}, %2;" : "=f"(lo), "=f"(hi) : "l"(v));
}
__device__ __forceinline__ void fma2(uint64_t& c, uint64_t a, uint64_t b) {
    asm("fma.rn.f32x2 %0, %1, %2, %0;" : "+l"(c) : "l"(a), "l"(b));
}

// ---------------------------------------------------------------------------
// CSR build
// ---------------------------------------------------------------------------
__global__ void k_zero_deg() {
    int i = blockIdx.x * blockDim.x + threadIdx.x;
    if (i < NN) g_deg[i] = 0;
}

__global__ void k_hist(const int* __restrict__ row, int E) {
    int i = blockIdx.x * blockDim.x + threadIdx.x;
    if (i < E) atomicAdd(&g_deg[row[i]], 1);
}

__global__ void k_scan() {
    __shared__ int sh[1024];
    __shared__ int s_run;
    if (threadIdx.x == 0) s_run = 0;
    __syncthreads();
    for (int base = 0; base < NN; base += 1024) {
        int i = base + (int)threadIdx.x;
        int v = (i < NN) ? g_deg[i] : 0;
        sh[threadIdx.x] = v;
        __syncthreads();
        for (int ofs = 1; ofs < 1024; ofs <<= 1) {
            int t = (threadIdx.x >= (unsigned)ofs) ? sh[threadIdx.x - ofs] : 0;
            __syncthreads();
            sh[threadIdx.x] += t;
            __syncthreads();
        }
        int run = s_run;
        if (i < NN) {
            int excl = run + sh[threadIdx.x] - v;
            g_rowstart[i] = excl;
            g_cursor[i]   = excl;
        }
        __syncthreads();
        if (threadIdx.x == 0) s_run = run + sh[1023];
        __syncthreads();
    }
    if (threadIdx.x == 0) g_rowstart[NN] = s_run;
}

__global__ void k_scatter(const int* __restrict__ row, const int* __restrict__ col,
                          const float* __restrict__ ws, const float* __restrict__ ent,
                          const float* __restrict__ cc, const float* __restrict__ q, int E) {
    int i = blockIdx.x * blockDim.x + threadIdx.x;
    if (i >= E) return;
    float ph = q[0] * (ent[i] + cc[i]);
    float s, c;
    sincosf(ph, &s, &c);
    float w = ws[i];
    int p = atomicAdd(&g_cursor[row[i]], 1);
    g_ccol[p] = col[i];
    g_cwr[p] = w * c;
    g_cwi[p] = w * s;
}

// ---------------------------------------------------------------------------
// CSR gather complex SpMM: warp = (row, 128-feature chunk); lane owns float4.
// 4-edge unrolled inner loop (8 independent gathers in flight).
// ---------------------------------------------------------------------------
__global__ void k_spmm(const float* __restrict__ Xr, const float* __restrict__ Xi,
                       float* __restrict__ Zr, float* __restrict__ Zi) {
    int gw   = (blockIdx.x * blockDim.x + threadIdx.x) >> 5;
    int lane = threadIdx.x & 31;
    int r = gw >> 1;
    if (r >= NN) return;
    int off = ((gw & 1) << 7) + (lane << 2);

    int s = g_rowstart[r], e = g_rowstart[r + 1];
    float4 ar = make_float4(0.f, 0.f, 0.f, 0.f);
    float4 ai = make_float4(0.f, 0.f, 0.f, 0.f);

    auto acc1 = [&](int c, float wr, float wi) {
        const float4 xr = *(const float4*)(Xr + (size_t)c * KF + off);
        const float4 xi = *(const float4*)(Xi + (size_t)c * KF + off);
        ar.x = fmaf(wr, xr.x, fmaf(-wi, xi.x, ar.x));
        ar.y = fmaf(wr, xr.y, fmaf(-wi, xi.y, ar.y));
        ar.z = fmaf(wr, xr.z, fmaf(-wi, xi.z, ar.z));
        ar.w = fmaf(wr, xr.w, fmaf(-wi, xi.w, ar.w));
        ai.x = fmaf(wi, xr.x, fmaf(wr, xi.x, ai.x));
        ai.y = fmaf(wi, xr.y, fmaf(wr, xi.y, ai.y));
        ai.z = fmaf(wi, xr.z, fmaf(wr, xi.z, ai.z));
        ai.w = fmaf(wi, xr.w, fmaf(wr, xi.w, ai.w));
    };

    int j = s;
    while (j < e && (j & 3)) { acc1(g_ccol[j], g_cwr[j], g_cwi[j]); j++; }
#pragma unroll 1
    for (; j + 4 <= e; j += 4) {
        const int4   c4  = *(const int4*)(g_ccol + j);
        const float4 wr4 = *(const float4*)(g_cwr + j);
        const float4 wi4 = *(const float4*)(g_cwi + j);
        const float4 xr0 = *(const float4*)(Xr + (size_t)c4.x * KF + off);
        const float4 xi0 = *(const float4*)(Xi + (size_t)c4.x * KF + off);
        const float4 xr1 = *(const float4*)(Xr + (size_t)c4.y * KF + off);
        const float4 xi1 = *(const float4*)(Xi + (size_t)c4.y * KF + off);
        const float4 xr2 = *(const float4*)(Xr + (size_t)c4.z * KF + off);
        const float4 xi2 = *(const float4*)(Xi + (size_t)c4.z * KF + off);
        const float4 xr3 = *(const float4*)(Xr + (size_t)c4.w * KF + off);
        const float4 xi3 = *(const float4*)(Xi + (size_t)c4.w * KF + off);
#define ACC(XR, XI, WR, WI)                                   \
        ar.x = fmaf(WR, XR.x, fmaf(-WI, XI.x, ar.x));         \
        ar.y = fmaf(WR, XR.y, fmaf(-WI, XI.y, ar.y));         \
        ar.z = fmaf(WR, XR.z, fmaf(-WI, XI.z, ar.z));         \
        ar.w = fmaf(WR, XR.w, fmaf(-WI, XI.w, ar.w));         \
        ai.x = fmaf(WI, XR.x, fmaf(WR, XI.x, ai.x));          \
        ai.y = fmaf(WI, XR.y, fmaf(WR, XI.y, ai.y));          \
        ai.z = fmaf(WI, XR.z, fmaf(WR, XI.z, ai.z));          \
        ai.w = fmaf(WI, XR.w, fmaf(WR, XI.w, ai.w));
        ACC(xr0, xi0, wr4.x, wi4.x)
        ACC(xr1, xi1, wr4.y, wi4.y)
        ACC(xr2, xi2, wr4.z, wi4.z)
        ACC(xr3, xi3, wr4.w, wi4.w)
#undef ACC
    }
    for (; j < e; j++) { acc1(g_ccol[j], g_cwr[j], g_cwi[j]); }

    *(float4*)(Zr + (size_t)r * KF + off) = ar;
    *(float4*)(Zi + (size_t)r * KF + off) = ai;
}

// ---------------------------------------------------------------------------
// Fused dual SGEMM via FFMA2, register-staged prefetch:
//   Or = mask * (Ar @ W^T), Oi = mask * (Ai @ W^T + 2*b), mask = (real >= 0)
// BM=128 BN=64 BK=16, 256 threads, thread tile 8(m) x 4(n) x 2 channels.
// Accumulators packed pairwise over M -> 32 FFMA2 + 4 movs per k-step.
// k-serial accumulation order identical to the R2 pass (bit-exact numerics).
// ---------------------------------------------------------------------------
__global__ void __launch_bounds__(256, 2)
k_gemm_dual(const float* __restrict__ Ar, const float* __restrict__ Ai,
            const float* __restrict__ W,  const float* __restrict__ bias,
            float* __restrict__ Or, float* __restrict__ Oi) {
    constexpr int BM = 128, BN = 64, BK = 16;
    __shared__ float As_r[BK][BM + 4];
    __shared__ float As_i[BK][BM + 4];
    __shared__ float Bs[BK][BN + 4];
    const int tid = threadIdx.x;
    const int tx = tid & 15, ty = tid >> 4;
    const int row0 = blockIdx.x * BM;
    const int col0 = blockIdx.y * BN;

    uint64_t accR[4][4], accI[4][4];
#pragma unroll
    for (int ip = 0; ip < 4; ip++)
#pragma unroll
        for (int j = 0; j < 4; j++) { accR[ip][j] = 0ull; accI[ip][j] = 0ull; }

    // prefetch registers
    float4 pr[2], pi[2], pb;
    const int lr0 = tid >> 2,        lkq = tid & 3;        // A scatter coords
    const int lr1 = (tid + 256) >> 2;
    const int br  = tid >> 2,        bkq = tid & 3;        // B scatter coords

    auto gload = [&](int k0) {
        int g0 = row0 + lr0; if (g0 >= NN) g0 = NN - 1;
        int g1 = row0 + lr1; if (g1 >= NN) g1 = NN - 1;
        pr[0] = *(const float4*)(Ar + (size_t)g0 * KF + k0 + lkq * 4);
        pr[1] = *(const float4*)(Ar + (size_t)g1 * KF + k0 + lkq * 4);
        pi[0] = *(const float4*)(Ai + (size_t)g0 * KF + k0 + lkq * 4);
        pi[1] = *(const float4*)(Ai + (size_t)g1 * KF + k0 + lkq * 4);
        pb    = *(const float4*)(W  + (size_t)(col0 + br) * KF + k0 + bkq * 4);
    };

    gload(0);
    for (int s = 0; s < KF / BK; s++) {
        // scatter prefetch regs into smem (A transposed: As[k][m])
        As_r[lkq*4+0][lr0] = pr[0].x; As_r[lkq*4+1][lr0] = pr[0].y;
        As_r[lkq*4+2][lr0] = pr[0].z; As_r[lkq*4+3][lr0] = pr[0].w;
        As_r[lkq*4+0][lr1] = pr[1].x; As_r[lkq*4+1][lr1] = pr[1].y;
        As_r[lkq*4+2][lr1] = pr[1].z; As_r[lkq*4+3][lr1] = pr[1].w;
        As_i[lkq*4+0][lr0] = pi[0].x; As_i[lkq*4+1][lr0] = pi[0].y;
        As_i[lkq*4+2][lr0] = pi[0].z; As_i[lkq*4+3][lr0] = pi[0].w;
        As_i[lkq*4+0][lr1] = pi[1].x; As_i[lkq*4+1][lr1] = pi[1].y;
        As_i[lkq*4+2][lr1] = pi[1].z; As_i[lkq*4+3][lr1] = pi[1].w;
        Bs[bkq*4+0][br] = pb.x; Bs[bkq*4+1][br] = pb.y;
        Bs[bkq*4+2][br] = pb.z; Bs[bkq*4+3][br] = pb.w;
        __syncthreads();

        if (s + 1 < KF / BK) gload((s + 1) * BK);   // overlap with compute

#pragma unroll
        for (int k = 0; k < BK; k++) {
            const float4 b4 = *(const float4*)&Bs[k][tx * 4];
            const uint64_t bd0 = pk2(b4.x, b4.x), bd1 = pk2(b4.y, b4.y);
            const uint64_t bd2 = pk2(b4.z, b4.z), bd3 = pk2(b4.w, b4.w);
            const uint64_t* par = (const uint64_t*)&As_r[k][ty * 8];
            const uint64_t* pai = (const uint64_t*)&As_i[k][ty * 8];
#pragma unroll
            for (int ip = 0; ip < 4; ip++) {
                const uint64_t a2r = par[ip];
                const uint64_t a2i = pai[ip];
                fma2(accR[ip][0], a2r, bd0); fma2(accR[ip][1], a2r, bd1);
                fma2(accR[ip][2], a2r, bd2); fma2(accR[ip][3], a2r, bd3);
                fma2(accI[ip][0], a2i, bd0); fma2(accI[ip][1], a2i, bd1);
                fma2(accI[ip][2], a2i, bd2); fma2(accI[ip][3], a2i, bd3);
            }
        }
        __syncthreads();
    }

    // epilogue: bias (imag only, x2), comrelu mask, store
    const float4 bv = *(const float4*)(bias + col0 + tx * 4);
    const float bvals[4] = {bv.x, bv.y, bv.z, bv.w};
#pragma unroll
    for (int ip = 0; ip < 4; ip++) {
        float rlo[4], rhi[4], ilo[4], ihi[4];
#pragma unroll
        for (int j = 0; j < 4; j++) {
            upk2(accR[ip][j], rlo[j], rhi[j]);
            upk2(accI[ip][j], ilo[j], ihi[j]);
        }
        const int gr0 = row0 + ty * 8 + 2 * ip;
#pragma unroll
        for (int h = 0; h < 2; h++) {
            const int gr = gr0 + h;
            if (gr < NN) {
                float ro[4], io[4];
#pragma unroll
                for (int j = 0; j < 4; j++) {
                    float rv = h ? rhi[j] : rlo[j];
                    float iv = (h ? ihi[j] : ilo[j]) + 2.f * bvals[j];
                    float m = (rv >= 0.f) ? 1.f : 0.f;
                    ro[j] = rv * m; io[j] = iv * m;
                }
                *(float4*)(Or + (size_t)gr * KF + col0 + tx * 4) =
                    make_float4(ro[0], ro[1], ro[2], ro[3]);
                *(float4*)(Oi + (size_t)gr * KF + col0 + tx * 4) =
                    make_float4(io[0], io[1], io[2], io[3]);
            }
        }
    }
}

// ---------------------------------------------------------------------------
// Head GEMM via FFMA2: out = Hr@W3[:, :256]^T + Hi@W3[:, 256:]^T + b3 (K=512)
// ---------------------------------------------------------------------------
__global__ void __launch_bounds__(256, 2)
k_gemm_head(const float* __restrict__ Hr, const float* __restrict__ Hi,
            const float* __restrict__ W3, const float* __restrict__ b3,
            float* __restrict__ out) {
    constexpr int BM = 128, BN = 64, BK = 16, NST = 32;
    __shared__ float As[BK][BM + 4];
    __shared__ float Bs[BK][BN + 4];
    const int tid = threadIdx.x;
    const int tx = tid & 15, ty = tid >> 4;
    const int row0 = blockIdx.x * BM;

    uint64_t acc[4][4];
#pragma unroll
    for (int ip = 0; ip < 4; ip++)
#pragma unroll
        for (int j = 0; j < 4; j++) acc[ip][j] = 0ull;

    float4 pa[2], pb;
    const int lr0 = tid >> 2,        lkq = tid & 3;
    const int lr1 = (tid + 256) >> 2;
    const int br  = tid >> 2,        bkq = tid & 3;

    auto gload = [&](int s) {
        const float* A = (s < 16) ? Hr : Hi;
        const int ko = (s & 15) * BK;
        int g0 = row0 + lr0; if (g0 >= NN) g0 = NN - 1;
        int g1 = row0 + lr1; if (g1 >= NN) g1 = NN - 1;
        pa[0] = *(const float4*)(A + (size_t)g0 * KF + ko + lkq * 4);
        pa[1] = *(const float4*)(A + (size_t)g1 * KF + ko + lkq * 4);
        pb    = *(const float4*)(W3 + (size_t)br * 512 + s * BK + bkq * 4);
    };

    gload(0);
    for (int s = 0; s < NST; s++) {
        As[lkq*4+0][lr0] = pa[0].x; As[lkq*4+1][lr0] = pa[0].y;
        As[lkq*4+2][lr0] = pa[0].z; As[lkq*4+3][lr0] = pa[0].w;
        As[lkq*4+0][lr1] = pa[1].x; As[lkq*4+1][lr1] = pa[1].y;
        As[lkq*4+2][lr1] = pa[1].z; As[lkq*4+3][lr1] = pa[1].w;
        Bs[bkq*4+0][br] = pb.x; Bs[bkq*4+1][br] = pb.y;
        Bs[bkq*4+2][br] = pb.z; Bs[bkq*4+3][br] = pb.w;
        __syncthreads();

        if (s + 1 < NST) gload(s + 1);

#pragma unroll
        for (int k = 0; k < BK; k++) {
            const float4 b4 = *(const float4*)&Bs[k][tx * 4];
            const uint64_t bd0 = pk2(b4.x, b4.x), bd1 = pk2(b4.y, b4.y);
            const uint64_t bd2 = pk2(b4.z, b4.z), bd3 = pk2(b4.w, b4.w);
            const uint64_t* pa2 = (const uint64_t*)&As[k][ty * 8];
#pragma unroll
            for (int ip = 0; ip < 4; ip++) {
                const uint64_t a2 = pa2[ip];
                fma2(acc[ip][0], a2, bd0); fma2(acc[ip][1], a2, bd1);
                fma2(acc[ip][2], a2, bd2); fma2(acc[ip][3], a2, bd3);
            }
        }
        __syncthreads();
    }

    const float4 bv = *(const float4*)(b3 + tx * 4);
    const float bvals[4] = {bv.x, bv.y, bv.z, bv.w};
#pragma unroll
    for (int ip = 0; ip < 4; ip++) {
        float lo[4], hi[4];
#pragma unroll
        for (int j = 0; j < 4; j++) upk2(acc[ip][j], lo[j], hi[j]);
        const int gr0 = row0 + ty * 8 + 2 * ip;
#pragma unroll
        for (int h = 0; h < 2; h++) {
            const int gr = gr0 + h;
            if (gr < NN) {
                float o[4];
#pragma unroll
                for (int j = 0; j < 4; j++)
                    o[j] = (h ? hi[j] : lo[j]) + bvals[j];
                *(float4*)(out + (size_t)gr * NO + tx * 4) =
                    make_float4(o[0], o[1], o[2], o[3]);
            }
        }
    }
}

// ---------------------------------------------------------------------------
extern "C" void kernel_launch(void* const* d_in, const int* in_sizes, int n_in,
                              void* d_out, int out_size) {
    const float* real = (const float*)d_in[0];
    const float* imag = (const float*)d_in[1];
    const int*   row  = (const int*)d_in[2];
    const int*   col  = (const int*)d_in[3];
    const float* ws   = (const float*)d_in[4];
    const float* ent  = (const float*)d_in[5];
    const float* cc   = (const float*)d_in[6];
    const float* q    = (const float*)d_in[7];
    const float* W1   = (const float*)d_in[8];
    const float* b1   = (const float*)d_in[9];
    const float* W2   = (const float*)d_in[10];
    const float* b2   = (const float*)d_in[11];
    const float* W3   = (const float*)d_in[12];
    const float* b3   = (const float*)d_in[13];
    float* out = (float*)d_out;
    const int E = in_sizes[2];

    void *pZr, *pZi, *pHr, *pHi;
    cudaGetSymbolAddress(&pZr, g_Zr);
    cudaGetSymbolAddress(&pZi, g_Zi);
    cudaGetSymbolAddress(&pHr, g_Hr);
    cudaGetSymbolAddress(&pHi, g_Hi);
    float* Zr = (float*)pZr; float* Zi = (float*)pZi;
    float* Hr = (float*)pHr; float* Hi = (float*)pHi;

    // CSR build
    k_zero_deg<<<(NN + 255) / 256, 256>>>();
    k_hist<<<(E + 255) / 256, 256>>>(row, E);
    k_scan<<<1, 1024>>>();
    k_scatter<<<(E + 255) / 256, 256>>>(row, col, ws, ent, cc, q, E);

    const int spmm_blocks = (NN * 2 + 7) / 8;   // 8 warps/block, 2 chunks/row
    dim3 gemm_grid((NN + 127) / 128, KF / 64);

    // layer 1
    k_spmm<<<spmm_blocks, 256>>>(real, imag, Zr, Zi);
    k_gemm_dual<<<gemm_grid, 256>>>(Zr, Zi, W1, b1, Hr, Hi);
    // layer 2
    k_spmm<<<spmm_blocks, 256>>>(Hr, Hi, Zr, Zi);
    k_gemm_dual<<<gemm_grid, 256>>>(Zr, Zi, W2, b2, Hr, Hi);
    // head
    k_gemm_head<<<(NN + 127) / 128, 256>>>(Hr, Hi, W3, b3, out);
}

// round 10
// speedup vs baseline: 1.5287x; 1.0163x over previous
#include <cuda_runtime.h>
#include <math.h>
#include <stdint.h>

// ---------------------------------------------------------------------------
// Complex 2-layer MAP graph convolution, fp32 (R2-exact numerics).
//   CSR build (multi-block scan, packed edges) -> complex SpMM (fp32,
//   register acc, MLP-8 unrolled float4-packed gathers) -> FFMA2 GEMM
//   (double-buffered smem, one sync/stage) -> head GEMM.
// ---------------------------------------------------------------------------

namespace {
constexpr int NN = 50000;     // nodes
constexpr int NE = 1600000;   // edges
constexpr int KF = 256;       // FEAT == HID
constexpr int NO = 64;        // OUT
constexpr int NSCB = (NN + 1023) / 1024;   // 49 scan chunks
}

// scratch (device globals: allocation-free by rule)
__device__ int    g_deg[NN];
__device__ int    g_cursor[NN];
__device__ int    g_rowstart[NN + 1];
__device__ int    g_bsum[64];
__device__ float4 g_edge[NE];             // {col_bits, wr, wi, pad}
__device__ float  g_Zr[(size_t)NN * KF];
__device__ float  g_Zi[(size_t)NN * KF];
__device__ float  g_Hr[(size_t)NN * KF];
__device__ float  g_Hi[(size_t)NN * KF];

// ---------------------------------------------------------------------------
// f32x2 packed helpers (Blackwell base ISA; RN per element == scalar fmaf)
// ---------------------------------------------------------------------------
__device__ __forceinline__ uint64_t pk2(float lo, float hi) {
    uint64_t r; asm("mov.b64 %0, {%1, %2};" : "=l"(r) : "f"(lo), "f"(hi)); return r;
}
__device__ __forceinline__ void upk2(uint64_t v, float& lo, float& hi) {
    asm("mov.b64 {%0, %1}, %2;" : "=f"(lo), "=f"(hi) : "l"(v));
}
__device__ __forceinline__ void fma2(uint64_t& c, uint64_t a, uint64_t b) {
    asm("fma.rn.f32x2 %0, %1, %2, %0;" : "+l"(c) : "l"(a), "l"(b));
}

// ---------------------------------------------------------------------------
// CSR build
// ---------------------------------------------------------------------------
__global__ void k_zero_deg() {
    int i = blockIdx.x * blockDim.x + threadIdx.x;
    if (i < NN) g_deg[i] = 0;
}

__global__ void k_hist(const int* __restrict__ row, int E) {
    int i = blockIdx.x * blockDim.x + threadIdx.x;
    if (i < E) atomicAdd(&g_deg[row[i]], 1);
}

// phase 1: per-chunk exclusive scan (1024/block), chunk total to g_bsum
__global__ void k_scan1() {
    __shared__ int sh[1024];
    const int b = blockIdx.x;
    const int i = b * 1024 + threadIdx.x;
    int v = (i < NN) ? g_deg[i] : 0;
    sh[threadIdx.x] = v;
    __syncthreads();
    for (int ofs = 1; ofs < 1024; ofs <<= 1) {
        int t = (threadIdx.x >= (unsigned)ofs) ? sh[threadIdx.x - ofs] : 0;
        __syncthreads();
        sh[threadIdx.x] += t;
        __syncthreads();
    }
    if (i < NN) g_rowstart[i] = sh[threadIdx.x] - v;   // chunk-local exclusive
    if (threadIdx.x == 1023) g_bsum[b] = sh[1023];
}

// phase 2: scan the chunk totals (one warp-sized block)
__global__ void k_scan2() {
    __shared__ int sh[64];
    int v = (threadIdx.x < NSCB) ? g_bsum[threadIdx.x] : 0;
    sh[threadIdx.x] = v;
    __syncthreads();
    for (int ofs = 1; ofs < 64; ofs <<= 1) {
        int t = (threadIdx.x >= (unsigned)ofs) ? sh[threadIdx.x - ofs] : 0;
        __syncthreads();
        sh[threadIdx.x] += t;
        __syncthreads();
    }
    if (threadIdx.x < NSCB) g_bsum[threadIdx.x] = sh[threadIdx.x] - v;  // exclusive
    if (threadIdx.x == 0) g_rowstart[NN] = sh[63];                      // total
}

// phase 3: add chunk offsets, init cursor
__global__ void k_scan3() {
    const int b = blockIdx.x;
    const int i = b * 1024 + threadIdx.x;
    if (i < NN) {
        int r = g_rowstart[i] + g_bsum[b];
        g_rowstart[i] = r;
        g_cursor[i]   = r;
    }
}

// per-edge trig weights + packed CSR scatter (single 16B store)
__global__ void k_scatter(const int* __restrict__ row, const int* __restrict__ col,
                          const float* __restrict__ ws, const float* __restrict__ ent,
                          const float* __restrict__ cc, const float* __restrict__ q, int E) {
    int i = blockIdx.x * blockDim.x + threadIdx.x;
    if (i >= E) return;
    float ph = q[0] * (ent[i] + cc[i]);
    float s, c;
    sincosf(ph, &s, &c);
    float w = ws[i];
    int p = atomicAdd(&g_cursor[row[i]], 1);
    g_edge[p] = make_float4(__int_as_float(col[i]), w * c, w * s, 0.f);
}

// ---------------------------------------------------------------------------
// CSR gather complex SpMM: warp = (row, 128-feature chunk); lane owns float4.
// 4-edge unrolled inner loop (8 independent feature gathers in flight).
// ---------------------------------------------------------------------------
__global__ void k_spmm(const float* __restrict__ Xr, const float* __restrict__ Xi,
                       float* __restrict__ Zr, float* __restrict__ Zi) {
    int gw   = (blockIdx.x * blockDim.x + threadIdx.x) >> 5;
    int lane = threadIdx.x & 31;
    int r = gw >> 1;
    if (r >= NN) return;
    int off = ((gw & 1) << 7) + (lane << 2);

    int s = g_rowstart[r], e = g_rowstart[r + 1];
    float4 ar = make_float4(0.f, 0.f, 0.f, 0.f);
    float4 ai = make_float4(0.f, 0.f, 0.f, 0.f);

    auto acc1 = [&](float4 ed) {
        int c = __float_as_int(ed.x);
        const float4 xr = *(const float4*)(Xr + (size_t)c * KF + off);
        const float4 xi = *(const float4*)(Xi + (size_t)c * KF + off);
        ar.x = fmaf(ed.y, xr.x, fmaf(-ed.z, xi.x, ar.x));
        ar.y = fmaf(ed.y, xr.y, fmaf(-ed.z, xi.y, ar.y));
        ar.z = fmaf(ed.y, xr.z, fmaf(-ed.z, xi.z, ar.z));
        ar.w = fmaf(ed.y, xr.w, fmaf(-ed.z, xi.w, ar.w));
        ai.x = fmaf(ed.z, xr.x, fmaf(ed.y, xi.x, ai.x));
        ai.y = fmaf(ed.z, xr.y, fmaf(ed.y, xi.y, ai.y));
        ai.z = fmaf(ed.z, xr.z, fmaf(ed.y, xi.z, ai.z));
        ai.w = fmaf(ed.z, xr.w, fmaf(ed.y, xi.w, ai.w));
    };

    int j = s;
    while (j < e && (j & 3)) { acc1(g_edge[j]); j++; }
#pragma unroll 1
    for (; j + 4 <= e; j += 4) {
        const float4 e0 = g_edge[j],     e1 = g_edge[j + 1];
        const float4 e2 = g_edge[j + 2], e3 = g_edge[j + 3];
        const int c0 = __float_as_int(e0.x), c1 = __float_as_int(e1.x);
        const int c2 = __float_as_int(e2.x), c3 = __float_as_int(e3.x);
        const float4 xr0 = *(const float4*)(Xr + (size_t)c0 * KF + off);
        const float4 xi0 = *(const float4*)(Xi + (size_t)c0 * KF + off);
        const float4 xr1 = *(const float4*)(Xr + (size_t)c1 * KF + off);
        const float4 xi1 = *(const float4*)(Xi + (size_t)c1 * KF + off);
        const float4 xr2 = *(const float4*)(Xr + (size_t)c2 * KF + off);
        const float4 xi2 = *(const float4*)(Xi + (size_t)c2 * KF + off);
        const float4 xr3 = *(const float4*)(Xr + (size_t)c3 * KF + off);
        const float4 xi3 = *(const float4*)(Xi + (size_t)c3 * KF + off);
#define ACC(XR, XI, WR, WI)                                   \
        ar.x = fmaf(WR, XR.x, fmaf(-WI, XI.x, ar.x));         \
        ar.y = fmaf(WR, XR.y, fmaf(-WI, XI.y, ar.y));         \
        ar.z = fmaf(WR, XR.z, fmaf(-WI, XI.z, ar.z));         \
        ar.w = fmaf(WR, XR.w, fmaf(-WI, XI.w, ar.w));         \
        ai.x = fmaf(WI, XR.x, fmaf(WR, XI.x, ai.x));          \
        ai.y = fmaf(WI, XR.y, fmaf(WR, XI.y, ai.y));          \
        ai.z = fmaf(WI, XR.z, fmaf(WR, XI.z, ai.z));          \
        ai.w = fmaf(WI, XR.w, fmaf(WR, XI.w, ai.w));
        ACC(xr0, xi0, e0.y, e0.z)
        ACC(xr1, xi1, e1.y, e1.z)
        ACC(xr2, xi2, e2.y, e2.z)
        ACC(xr3, xi3, e3.y, e3.z)
#undef ACC
    }
    for (; j < e; j++) { acc1(g_edge[j]); }

    *(float4*)(Zr + (size_t)r * KF + off) = ar;
    *(float4*)(Zi + (size_t)r * KF + off) = ai;
}

// ---------------------------------------------------------------------------
// Fused dual SGEMM via FFMA2, double-buffered smem (one sync per stage):
//   Or = mask * (Ar @ W^T), Oi = mask * (Ai @ W^T + 2*b), mask = (real >= 0)
// BM=128 BN=64 BK=16, 256 threads, thread tile 8(m) x 4(n) x 2 channels.
// k-serial accumulation order identical to the R2/R9 pass (bit-exact).
// ---------------------------------------------------------------------------
__global__ void __launch_bounds__(256, 2)
k_gemm_dual(const float* __restrict__ Ar, const float* __restrict__ Ai,
            const float* __restrict__ W,  const float* __restrict__ bias,
            float* __restrict__ Or, float* __restrict__ Oi) {
    constexpr int BM = 128, BN = 64, BK = 16, S = KF / BK;
    __shared__ float As_r[2][BK][BM + 4];
    __shared__ float As_i[2][BK][BM + 4];
    __shared__ float Bs[2][BK][BN + 4];
    const int tid = threadIdx.x;
    const int tx = tid & 15, ty = tid >> 4;
    const int row0 = blockIdx.x * BM;
    const int col0 = blockIdx.y * BN;

    uint64_t accR[4][4], accI[4][4];
#pragma unroll
    for (int ip = 0; ip < 4; ip++)
#pragma unroll
        for (int j = 0; j < 4; j++) { accR[ip][j] = 0ull; accI[ip][j] = 0ull; }

    float4 pr[2], pi[2], pb;
    const int lr0 = tid >> 2,        lkq = tid & 3;
    const int lr1 = (tid + 256) >> 2;
    const int br  = tid >> 2,        bkq = tid & 3;

    auto gload = [&](int k0) {
        int g0 = row0 + lr0; if (g0 >= NN) g0 = NN - 1;
        int g1 = row0 + lr1; if (g1 >= NN) g1 = NN - 1;
        pr[0] = *(const float4*)(Ar + (size_t)g0 * KF + k0 + lkq * 4);
        pr[1] = *(const float4*)(Ar + (size_t)g1 * KF + k0 + lkq * 4);
        pi[0] = *(const float4*)(Ai + (size_t)g0 * KF + k0 + lkq * 4);
        pi[1] = *(const float4*)(Ai + (size_t)g1 * KF + k0 + lkq * 4);
        pb    = *(const float4*)(W  + (size_t)(col0 + br) * KF + k0 + bkq * 4);
    };
    auto sstore = [&](int buf) {
        As_r[buf][lkq*4+0][lr0] = pr[0].x; As_r[buf][lkq*4+1][lr0] = pr[0].y;
        As_r[buf][lkq*4+2][lr0] = pr[0].z; As_r[buf][lkq*4+3][lr0] = pr[0].w;
        As_r[buf][lkq*4+0][lr1] = pr[1].x; As_r[buf][lkq*4+1][lr1] = pr[1].y;
        As_r[buf][lkq*4+2][lr1] = pr[1].z; As_r[buf][lkq*4+3][lr1] = pr[1].w;
        As_i[buf][lkq*4+0][lr0] = pi[0].x; As_i[buf][lkq*4+1][lr0] = pi[0].y;
        As_i[buf][lkq*4+2][lr0] = pi[0].z; As_i[buf][lkq*4+3][lr0] = pi[0].w;
        As_i[buf][lkq*4+0][lr1] = pi[1].x; As_i[buf][lkq*4+1][lr1] = pi[1].y;
        As_i[buf][lkq*4+2][lr1] = pi[1].z; As_i[buf][lkq*4+3][lr1] = pi[1].w;
        Bs[buf][bkq*4+0][br] = pb.x; Bs[buf][bkq*4+1][br] = pb.y;
        Bs[buf][bkq*4+2][br] = pb.z; Bs[buf][bkq*4+3][br] = pb.w;
    };

    gload(0);
    sstore(0);
    __syncthreads();
    for (int s = 0; s < S; s++) {
        if (s + 1 < S) gload((s + 1) * BK);
        const int buf = s & 1;
#pragma unroll
        for (int k = 0; k < BK; k++) {
            const float4 b4 = *(const float4*)&Bs[buf][k][tx * 4];
            const uint64_t bd0 = pk2(b4.x, b4.x), bd1 = pk2(b4.y, b4.y);
            const uint64_t bd2 = pk2(b4.z, b4.z), bd3 = pk2(b4.w, b4.w);
            const uint64_t* par = (const uint64_t*)&As_r[buf][k][ty * 8];
            const uint64_t* pai = (const uint64_t*)&As_i[buf][k][ty * 8];
#pragma unroll
            for (int ip = 0; ip < 4; ip++) {
                const uint64_t a2r = par[ip];
                const uint64_t a2i = pai[ip];
                fma2(accR[ip][0], a2r, bd0); fma2(accR[ip][1], a2r, bd1);
                fma2(accR[ip][2], a2r, bd2); fma2(accR[ip][3], a2r, bd3);
                fma2(accI[ip][0], a2i, bd0); fma2(accI[ip][1], a2i, bd1);
                fma2(accI[ip][2], a2i, bd2); fma2(accI[ip][3], a2i, bd3);
            }
        }
        if (s + 1 < S) sstore((s + 1) & 1);
        __syncthreads();
    }

    // epilogue: bias (imag only, x2), comrelu mask, store
    const float4 bv = *(const float4*)(bias + col0 + tx * 4);
    const float bvals[4] = {bv.x, bv.y, bv.z, bv.w};
#pragma unroll
    for (int ip = 0; ip < 4; ip++) {
        float rlo[4], rhi[4], ilo[4], ihi[4];
#pragma unroll
        for (int j = 0; j < 4; j++) {
            upk2(accR[ip][j], rlo[j], rhi[j]);
            upk2(accI[ip][j], ilo[j], ihi[j]);
        }
        const int gr0 = row0 + ty * 8 + 2 * ip;
#pragma unroll
        for (int h = 0; h < 2; h++) {
            const int gr = gr0 + h;
            if (gr < NN) {
                float ro[4], io[4];
#pragma unroll
                for (int j = 0; j < 4; j++) {
                    float rv = h ? rhi[j] : rlo[j];
                    float iv = (h ? ihi[j] : ilo[j]) + 2.f * bvals[j];
                    float m = (rv >= 0.f) ? 1.f : 0.f;
                    ro[j] = rv * m; io[j] = iv * m;
                }
                *(float4*)(Or + (size_t)gr * KF + col0 + tx * 4) =
                    make_float4(ro[0], ro[1], ro[2], ro[3]);
                *(float4*)(Oi + (size_t)gr * KF + col0 + tx * 4) =
                    make_float4(io[0], io[1], io[2], io[3]);
            }
        }
    }
}

// ---------------------------------------------------------------------------
// Head GEMM via FFMA2 (double-buffered):
//   out = Hr@W3[:, :256]^T + Hi@W3[:, 256:]^T + b3  (K=512)
// ---------------------------------------------------------------------------
__global__ void __launch_bounds__(256, 2)
k_gemm_head(const float* __restrict__ Hr, const float* __restrict__ Hi,
            const float* __restrict__ W3, const float* __restrict__ b3,
            float* __restrict__ out) {
    constexpr int BM = 128, BN = 64, BK = 16, NST = 32;
    __shared__ float As[2][BK][BM + 4];
    __shared__ float Bs[2][BK][BN + 4];
    const int tid = threadIdx.x;
    const int tx = tid & 15, ty = tid >> 4;
    const int row0 = blockIdx.x * BM;

    uint64_t acc[4][4];
#pragma unroll
    for (int ip = 0; ip < 4; ip++)
#pragma unroll
        for (int j = 0; j < 4; j++) acc[ip][j] = 0ull;

    float4 pa[2], pb;
    const int lr0 = tid >> 2,        lkq = tid & 3;
    const int lr1 = (tid + 256) >> 2;
    const int br  = tid >> 2,        bkq = tid & 3;

    auto gload = [&](int s) {
        const float* A = (s < 16) ? Hr : Hi;
        const int ko = (s & 15) * BK;
        int g0 = row0 + lr0; if (g0 >= NN) g0 = NN - 1;
        int g1 = row0 + lr1; if (g1 >= NN) g1 = NN - 1;
        pa[0] = *(const float4*)(A + (size_t)g0 * KF + ko + lkq * 4);
        pa[1] = *(const float4*)(A + (size_t)g1 * KF + ko + lkq * 4);
        pb    = *(const float4*)(W3 + (size_t)br * 512 + s * BK + bkq * 4);
    };
    auto sstore = [&](int buf) {
        As[buf][lkq*4+0][lr0] = pa[0].x; As[buf][lkq*4+1][lr0] = pa[0].y;
        As[buf][lkq*4+2][lr0] = pa[0].z; As[buf][lkq*4+3][lr0] = pa[0].w;
        As[buf][lkq*4+0][lr1] = pa[1].x; As[buf][lkq*4+1][lr1] = pa[1].y;
        As[buf][lkq*4+2][lr1] = pa[1].z; As[buf][lkq*4+3][lr1] = pa[1].w;
        Bs[buf][bkq*4+0][br] = pb.x; Bs[buf][bkq*4+1][br] = pb.y;
        Bs[buf][bkq*4+2][br] = pb.z; Bs[buf][bkq*4+3][br] = pb.w;
    };

    gload(0);
    sstore(0);
    __syncthreads();
    for (int s = 0; s < NST; s++) {
        if (s + 1 < NST) gload(s + 1);
        const int buf = s & 1;
#pragma unroll
        for (int k = 0; k < BK; k++) {
            const float4 b4 = *(const float4*)&Bs[buf][k][tx * 4];
            const uint64_t bd0 = pk2(b4.x, b4.x), bd1 = pk2(b4.y, b4.y);
            const uint64_t bd2 = pk2(b4.z, b4.z), bd3 = pk2(b4.w, b4.w);
            const uint64_t* pa2 = (const uint64_t*)&As[buf][k][ty * 8];
#pragma unroll
            for (int ip = 0; ip < 4; ip++) {
                const uint64_t a2 = pa2[ip];
                fma2(acc[ip][0], a2, bd0); fma2(acc[ip][1], a2, bd1);
                fma2(acc[ip][2], a2, bd2); fma2(acc[ip][3], a2, bd3);
            }
        }
        if (s + 1 < NST) sstore((s + 1) & 1);
        __syncthreads();
    }

    const float4 bv = *(const float4*)(b3 + tx * 4);
    const float bvals[4] = {bv.x, bv.y, bv.z, bv.w};
#pragma unroll
    for (int ip = 0; ip < 4; ip++) {
        float lo[4], hi[4];
#pragma unroll
        for (int j = 0; j < 4; j++) upk2(acc[ip][j], lo[j], hi[j]);
        const int gr0 = row0 + ty * 8 + 2 * ip;
#pragma unroll
        for (int h = 0; h < 2; h++) {
            const int gr = gr0 + h;
            if (gr < NN) {
                float o[4];
#pragma unroll
                for (int j = 0; j < 4; j++)
                    o[j] = (h ? hi[j] : lo[j]) + bvals[j];
                *(float4*)(out + (size_t)gr * NO + tx * 4) =
                    make_float4(o[0], o[1], o[2], o[3]);
            }
        }
    }
}

// ---------------------------------------------------------------------------
extern "C" void kernel_launch(void* const* d_in, const int* in_sizes, int n_in,
                              void* d_out, int out_size) {
    const float* real = (const float*)d_in[0];
    const float* imag = (const float*)d_in[1];
    const int*   row  = (const int*)d_in[2];
    const int*   col  = (const int*)d_in[3];
    const float* ws   = (const float*)d_in[4];
    const float* ent  = (const float*)d_in[5];
    const float* cc   = (const float*)d_in[6];
    const float* q    = (const float*)d_in[7];
    const float* W1   = (const float*)d_in[8];
    const float* b1   = (const float*)d_in[9];
    const float* W2   = (const float*)d_in[10];
    const float* b2   = (const float*)d_in[11];
    const float* W3   = (const float*)d_in[12];
    const float* b3   = (const float*)d_in[13];
    float* out = (float*)d_out;
    const int E = in_sizes[2];

    void *pZr, *pZi, *pHr, *pHi;
    cudaGetSymbolAddress(&pZr, g_Zr);
    cudaGetSymbolAddress(&pZi, g_Zi);
    cudaGetSymbolAddress(&pHr, g_Hr);
    cudaGetSymbolAddress(&pHi, g_Hi);
    float* Zr = (float*)pZr; float* Zi = (float*)pZi;
    float* Hr = (float*)pHr; float* Hi = (float*)pHi;

    // CSR build
    k_zero_deg<<<(NN + 255) / 256, 256>>>();
    k_hist<<<(E + 255) / 256, 256>>>(row, E);
    k_scan1<<<NSCB, 1024>>>();
    k_scan2<<<1, 64>>>();
    k_scan3<<<NSCB, 1024>>>();
    k_scatter<<<(E + 255) / 256, 256>>>(row, col, ws, ent, cc, q, E);

    const int spmm_blocks = (NN * 2 + 7) / 8;   // 8 warps/block, 2 chunks/row
    dim3 gemm_grid((NN + 127) / 128, KF / 64);

    // layer 1
    k_spmm<<<spmm_blocks, 256>>>(real, imag, Zr, Zi);
    k_gemm_dual<<<gemm_grid, 256>>>(Zr, Zi, W1, b1, Hr, Hi);
    // layer 2
    k_spmm<<<spmm_blocks, 256>>>(Hr, Hi, Zr, Zi);
    k_gemm_dual<<<gemm_grid, 256>>>(Zr, Zi, W2, b2, Hr, Hi);
    // head
    k_gemm_head<<<(NN + 127) / 128, 256>>>(Hr, Hi, W3, b3, out);
}